// round 5
// baseline (speedup 1.0000x reference)
#include <cuda_runtime.h>
#include <cuda_bf16.h>
#include <math.h>

// Problem constants
#define B_ROWS   2048
#define DDIM     128
#define NFEAT    100000
// Tiling
#define MT       64
#define NT       32
#define NSPLIT   18
#define NTILES   (NFEAT / NT)              // 3125 exactly (3125*32 = 100000)
// exp(dot/0.05 - 20) = 2^(dot*COEF - COEF), COEF = 20*log2(e)
#define COEF     28.85390081777927f
#define INV_TEMP 20.0f

// Scratch (device globals; no allocation allowed)
__device__ float g_inorm[B_ROWS * DDIM];        // normalized inputs
__device__ float g_partial[NSPLIT * B_ROWS];    // partial exp-sums per split

__device__ __forceinline__ float ex2f(float x) {
    float y;
    asm("ex2.approx.f32 %0, %1;" : "=f"(y) : "f"(x));
    return y;
}

// Width-dispatched integer load: idx arrays may be int32 or int64 depending on
// the reference framework's x64 setting. Detected at runtime (see kfinal).
__device__ __forceinline__ long long load_index(const void* p, int i, int is64) {
    if (is64) return ((const long long*)p)[i];
    return (long long)((const int*)p)[i];
}

// Sniff: little-endian int64 values in [0, NFEAT) have all odd 32-bit words
// zero; int32 arrays have random values there. Samples 32 odd words, all at
// word index < nelem so the read is in-bounds under BOTH dtype hypotheses
// (i32 buffer = nelem words; i64 buffer = 2*nelem words).
__device__ __forceinline__ int sniff_is64(const void* p, int nelem) {
    const int* w = (const int*)p;
    int half = nelem / 2;                    // elements we may safely probe
    int stride = half / 32;
    int allzero = 1;
    #pragma unroll
    for (int i = 0; i < 32; i++) {
        int e = i * stride;                  // e < half  =>  2e+1 < nelem
        if (w[2 * e + 1] != 0) allzero = 0;
    }
    return allzero;
}

// ---------------------------------------------------------------------------
// Kernel 1: L2-normalize each input row (matches x / max(||x||, 1e-12))
// ---------------------------------------------------------------------------
__global__ void knorm(const float* __restrict__ in) {
    int row = blockIdx.x;
    int t = threadIdx.x;                 // 128 threads = 1 row
    float v = in[row * DDIM + t];
    float ss = v * v;
    #pragma unroll
    for (int o = 16; o; o >>= 1) ss += __shfl_xor_sync(0xffffffffu, ss, o);
    __shared__ float ws[4];
    if ((t & 31) == 0) ws[t >> 5] = ss;
    __syncthreads();
    float tot = ws[0] + ws[1] + ws[2] + ws[3];
    float inv = 1.0f / fmaxf(sqrtf(tot), 1e-12f);
    g_inorm[row * DDIM + t] = v * inv;
}

// ---------------------------------------------------------------------------
// Kernel 2: main GEMM + online sum of exp(logit - 20)
// Grid: (NSPLIT, B_ROWS/MT). CTA: 256 threads. Tile M=64, N=32, K=128.
// Smem layout: [row][32 float4 chunks], chunk swizzled by (chunk ^ (row&7))
// Thread (tx,ty): rows {ty+16i}, cols {tx+16j} (strided => conflict-free LDS)
// B-tile global loads are software-pipelined: fetch tile t+1 into registers
// BEFORE computing tile t, store to smem after the barrier.
// ---------------------------------------------------------------------------
__global__ void __launch_bounds__(256, 4)
kmain(const float* __restrict__ feats) {
    __shared__ float smem[(MT + NT) * DDIM];     // 48 KB
    float4* As4 = (float4*)smem;                  // 64 rows * 32 chunks
    float4* Bs4 = (float4*)(smem + MT * DDIM);    // 32 rows * 32 chunks

    int tid = threadIdx.x;
    int split = blockIdx.x;
    int mt = blockIdx.y;
    int tx = tid & 15, ty = tid >> 4;
    int sa = ty & 7, sb = tx & 7;

    // Load A tile once (reused for the whole N loop), swizzled
    {
        const float4* src = (const float4*)(g_inorm + mt * MT * DDIM);
        #pragma unroll
        for (int i = 0; i < 8; i++) {
            int idx = i * 256 + tid;
            int c = idx & 31, r = idx >> 5;          // r: 0..63
            As4[r * 32 + (c ^ (r & 7))] = src[r * 32 + c];
        }
    }

    // Per-thread B-load coordinates (4 chunks per thread per tile)
    int lc[4], lr[4];
    #pragma unroll
    for (int i = 0; i < 4; i++) {
        int idx = i * 256 + tid;
        lc[i] = idx & 31;
        lr[i] = idx >> 5;                            // 0..31
    }

    float sacc[4] = {0.f, 0.f, 0.f, 0.f};

    // Prefetch first tile into registers
    float4 pre[4];
    {
        int n0 = split * NT;
        #pragma unroll
        for (int i = 0; i < 4; i++)
            pre[i] = __ldg(&((const float4*)feats)[(n0 + lr[i]) * 32 + lc[i]]);
    }

    for (int t = split; t < NTILES; t += NSPLIT) {
        __syncthreads();   // previous compute done (also covers A-load on iter 0)
        #pragma unroll
        for (int i = 0; i < 4; i++)
            Bs4[lr[i] * 32 + (lc[i] ^ (lr[i] & 7))] = pre[i];
        __syncthreads();

        // Prefetch next tile (overlaps with the FFMA block below).
        // Clamp instead of branch: out-of-range iterations re-load tile 'split'
        // (harmless; values never stored because the loop exits first).
        int tn = t + NSPLIT;
        int n1 = (tn < NTILES ? tn : split) * NT;
        #pragma unroll
        for (int i = 0; i < 4; i++)
            pre[i] = __ldg(&((const float4*)feats)[(n1 + lr[i]) * 32 + lc[i]]);

        float acc[4][2];
        #pragma unroll
        for (int i = 0; i < 4; i++)
            #pragma unroll
            for (int j = 0; j < 2; j++) acc[i][j] = 0.f;

        #pragma unroll
        for (int kq = 0; kq < 32; kq++) {
            float4 a[4], b[2];
            #pragma unroll
            for (int i = 0; i < 4; i++) a[i] = As4[(16 * i + ty) * 32 + (kq ^ sa)];
            #pragma unroll
            for (int j = 0; j < 2; j++) b[j] = Bs4[(16 * j + tx) * 32 + (kq ^ sb)];
            #pragma unroll
            for (int i = 0; i < 4; i++)
                #pragma unroll
                for (int j = 0; j < 2; j++) {
                    acc[i][j] = fmaf(a[i].x, b[j].x, acc[i][j]);
                    acc[i][j] = fmaf(a[i].y, b[j].y, acc[i][j]);
                    acc[i][j] = fmaf(a[i].z, b[j].z, acc[i][j]);
                    acc[i][j] = fmaf(a[i].w, b[j].w, acc[i][j]);
                }
        }

        // Fold this tile's logits into the running exp-sum (fixed shift 20)
        #pragma unroll
        for (int i = 0; i < 4; i++) {
            sacc[i] += ex2f(fmaf(acc[i][0], COEF, -COEF));
            sacc[i] += ex2f(fmaf(acc[i][1], COEF, -COEF));
        }
    }

    // Reduce sacc across the 16 tx threads sharing each row; write partials
    __syncthreads();
    float* red = smem;                               // reuse As region: 64 x 16
    #pragma unroll
    for (int i = 0; i < 4; i++) red[(16 * i + ty) * 16 + tx] = sacc[i];
    __syncthreads();
    if (tid < MT) {
        float s = 0.f;
        #pragma unroll
        for (int x = 0; x < 16; x++) s += red[tid * 16 + x];
        g_partial[split * B_ROWS + mt * MT + tid] = s;
    }
}

// ---------------------------------------------------------------------------
// Kernel 3: combine partials, compute picked logits, reduce loss (1 CTA,
// fixed-order reductions => deterministic). Integer dtype (i32 vs i64) is
// sniffed at runtime; target index clamped as a hard safety bound.
// ---------------------------------------------------------------------------
__global__ void kfinal(const float* __restrict__ feats,
                       const void* __restrict__ indexes,
                       const void* __restrict__ labels,
                       float* __restrict__ out) {
    __shared__ int s_is64_idx, s_is64_lab;
    int tid = threadIdx.x;              // 1024 threads = 32 warps
    int lane = tid & 31, w = tid >> 5;

    if (tid == 0) {
        s_is64_idx = sniff_is64(indexes, B_ROWS);
        s_is64_lab = sniff_is64(labels, NFEAT);
    }
    __syncthreads();
    int i64i = s_is64_idx, i64l = s_is64_lab;

    float local = 0.f;
    for (int b = w * 64; b < (w + 1) * 64; ++b) {
        // total exp-sum over splits
        float s = (lane < NSPLIT) ? g_partial[lane * B_ROWS + b] : 0.f;
        #pragma unroll
        for (int o = 16; o; o >>= 1) s += __shfl_xor_sync(0xffffffffu, s, o);
        // picked logit: 20 * dot(inputs_n[b], features[labels[indexes[b]]])
        long long ix = load_index(indexes, b, i64i);
        if (ix < 0) ix = 0; if (ix >= NFEAT) ix = NFEAT - 1;
        long long tgt = load_index(labels, (int)ix, i64l);
        if (tgt < 0) tgt = 0; if (tgt >= NFEAT) tgt = NFEAT - 1;
        const float* fr = feats + (size_t)tgt * DDIM;
        const float* ir = g_inorm + b * DDIM;
        float d = 0.f;
        #pragma unroll
        for (int k = 0; k < 4; k++) d = fmaf(ir[lane + 32 * k], fr[lane + 32 * k], d);
        #pragma unroll
        for (int o = 16; o; o >>= 1) d += __shfl_xor_sync(0xffffffffu, d, o);
        if (lane == 0) local += (20.0f + logf(s)) - INV_TEMP * d;
    }
    __shared__ float ws[32];
    if (lane == 0) ws[w] = local;
    __syncthreads();
    if (tid == 0) {
        float tot = 0.f;
        #pragma unroll
        for (int i = 0; i < 32; i++) tot += ws[i];
        out[0] = tot * (1.0f / (float)B_ROWS);
    }
}

// ---------------------------------------------------------------------------
extern "C" void kernel_launch(void* const* d_in, const int* in_sizes, int n_in,
                              void* d_out, int out_size) {
    // Map inputs by element count (robust to metadata ordering):
    // inputs 262144, indexes 2048, labels 100000, features 12800000
    const float* inputs = nullptr;
    const void* indexes = nullptr;
    const void* labels = nullptr;
    const float* feats = nullptr;
    for (int i = 0; i < n_in; i++) {
        switch (in_sizes[i]) {
            case B_ROWS * DDIM:  inputs  = (const float*)d_in[i]; break;
            case B_ROWS:         indexes = d_in[i];               break;
            case NFEAT:          labels  = d_in[i];               break;
            case NFEAT * DDIM:   feats   = (const float*)d_in[i]; break;
        }
    }

    knorm<<<B_ROWS, DDIM>>>(inputs);
    dim3 grid(NSPLIT, B_ROWS / MT);
    kmain<<<grid, 256>>>(feats);
    kfinal<<<1, 1024>>>(feats, indexes, labels, (float*)d_out);
}

// round 12
// speedup vs baseline: 10.2381x; 10.2381x over previous
#include <cuda_runtime.h>
#include <cuda_bf16.h>
#include <math.h>
#include <stdint.h>

// Problem constants
#define B_ROWS   2048
#define DDIM     128
#define NFEAT    100000
#define NSPLIT   18
#define NTILE    782            // ceil(100000/128)
#define NFPAD    (NTILE * 128)  // 100096
#define MGRPS    8              // 8 * 256 = 2048 rows
#define COEF     28.85390081777927f

// Scratch (device globals; no allocation allowed)
__device__ float          g_inorm[B_ROWS * DDIM];
__device__ __nv_bfloat16  g_abf[B_ROWS * DDIM];
__device__ __nv_bfloat16  g_fbf[NFPAD * DDIM];
__device__ float          g_partial[NSPLIT * B_ROWS];
__device__ float          g_loss[B_ROWS];

__device__ __forceinline__ float ex2f(float x) {
    float y; asm("ex2.approx.f32 %0, %1;" : "=f"(y) : "f"(x)); return y;
}
__device__ __forceinline__ uint32_t smem_u32(const void* p) {
    uint32_t a;
    asm("{ .reg .u64 t; cvta.to.shared.u64 t, %1; cvt.u32.u64 %0, t; }" : "=r"(a) : "l"(p));
    return a;
}
#define LDSM4(r, addr) \
    asm volatile("ldmatrix.sync.aligned.m8n8.x4.shared.b16 {%0,%1,%2,%3}, [%4];" \
        : "=r"((r)[0]), "=r"((r)[1]), "=r"((r)[2]), "=r"((r)[3]) : "r"(addr))
#define MMA16816(c, a, b0, b1) \
    asm volatile("mma.sync.aligned.m16n8k16.row.col.f32.bf16.bf16.f32 " \
        "{%0,%1,%2,%3},{%4,%5,%6,%7},{%8,%9},{%0,%1,%2,%3};" \
        : "+f"((c)[0]), "+f"((c)[1]), "+f"((c)[2]), "+f"((c)[3]) \
        : "r"((a)[0]), "r"((a)[1]), "r"((a)[2]), "r"((a)[3]), "r"(b0), "r"(b1))
#define CP_ASYNC16(dst, src) \
    asm volatile("cp.async.cg.shared.global [%0], [%1], 16;" :: "r"(dst), "l"(src))
#define CP_COMMIT() asm volatile("cp.async.commit_group;" ::: "memory")
#define CP_WAIT0()  asm volatile("cp.async.wait_group 0;" ::: "memory")

// int dtype handling (proven in R5)
__device__ __forceinline__ long long load_index(const void* p, int i, int is64) {
    if (is64) return ((const long long*)p)[i];
    return (long long)((const int*)p)[i];
}
__device__ __forceinline__ int sniff_is64(const void* p, int nelem) {
    const int* w = (const int*)p;
    int half = nelem / 2, stride = half / 32, allzero = 1;
    #pragma unroll
    for (int i = 0; i < 32; i++) if (w[2 * (i * stride) + 1] != 0) allzero = 0;
    return allzero;
}

// ---------------------------------------------------------------------------
// Kernel 1: normalize input rows; emit fp32 + bf16
// ---------------------------------------------------------------------------
__global__ void knorm(const float* __restrict__ in) {
    int row = blockIdx.x, t = threadIdx.x;
    float v = in[row * DDIM + t];
    float ss = v * v;
    #pragma unroll
    for (int o = 16; o; o >>= 1) ss += __shfl_xor_sync(0xffffffffu, ss, o);
    __shared__ float ws[4];
    if ((t & 31) == 0) ws[t >> 5] = ss;
    __syncthreads();
    float inv = 1.0f / fmaxf(sqrtf(ws[0] + ws[1] + ws[2] + ws[3]), 1e-12f);
    float nv = v * inv;
    g_inorm[row * DDIM + t] = nv;
    g_abf[row * DDIM + t] = __float2bfloat16_rn(nv);
}

// ---------------------------------------------------------------------------
// Kernel 1b: features fp32 -> padded bf16 (8 elems/thread; pad rows zeroed)
// ---------------------------------------------------------------------------
__global__ void kcvt(const float* __restrict__ feats) {
    long long base = ((long long)blockIdx.x * 256 + threadIdx.x) * 8;
    __nv_bfloat162 o[4];
    if (base < (long long)NFEAT * DDIM) {
        float4 v0 = *(const float4*)(feats + base);
        float4 v1 = *(const float4*)(feats + base + 4);
        o[0] = __floats2bfloat162_rn(v0.x, v0.y);
        o[1] = __floats2bfloat162_rn(v0.z, v0.w);
        o[2] = __floats2bfloat162_rn(v1.x, v1.y);
        o[3] = __floats2bfloat162_rn(v1.z, v1.w);
    } else {
        o[0] = o[1] = o[2] = o[3] = __floats2bfloat162_rn(0.f, 0.f);
    }
    *(uint4*)(g_fbf + base) = *(uint4*)o;
}

// ---------------------------------------------------------------------------
// Kernel 2: bf16 mma.sync GEMM + exp-sum epilogue.
// Grid (NSPLIT, MGRPS), 512 threads (16 warps, 4M x 4N warp grid).
// CTA tile M=256, N=128, K=128. A resident (64KB); B double-buffered via
// cp.async (2x32KB); XOR-swizzled 16B chunks -> conflict-free ldmatrix.
// ---------------------------------------------------------------------------
__global__ void __launch_bounds__(512, 1)
kmma() {
    extern __shared__ char smem[];
    const int SA = 0, SB = 65536, SR = 131072;   // A 64K | B 2x32K | red 4K
    uint32_t sb = smem_u32(smem);
    int tid = threadIdx.x, wid = tid >> 5, lane = tid & 31;
    int warpM = wid >> 2, warpN = wid & 3;
    int split = blockIdx.x, mgrp = blockIdx.y;

    // B cp.async addressing: 4 chunks/thread/tile
    const char* gsrc[4]; uint32_t sdst[4];
    #pragma unroll
    for (int i = 0; i < 4; i++) {
        int ch = i * 512 + tid;
        int r = ch >> 4, c = ch & 15;
        gsrc[i] = (const char*)(g_fbf + ((size_t)(split * 128 + r)) * DDIM + c * 8);
        sdst[i] = sb + SB + r * 256 + ((c ^ (r & 7)) << 4);
    }
    const size_t gstep = (size_t)NSPLIT * 128 * DDIM * sizeof(__nv_bfloat16);

    // Issue B tile 0 -> buf 0 (in flight during A load)
    #pragma unroll
    for (int i = 0; i < 4; i++) CP_ASYNC16(sdst[i], gsrc[i]);
    CP_COMMIT();
    #pragma unroll
    for (int i = 0; i < 4; i++) gsrc[i] += gstep;

    // Load A tile: 256 rows x 16 chunks (swizzled), 8 chunks/thread
    #pragma unroll
    for (int i = 0; i < 8; i++) {
        int ch = i * 512 + tid;
        int r = ch >> 4, c = ch & 15;
        uint4 v = *(const uint4*)(g_abf + ((size_t)(mgrp * 256 + r)) * DDIM + c * 8);
        *(uint4*)(smem + SA + r * 256 + ((c ^ (r & 7)) << 4)) = v;
    }
    CP_WAIT0();
    __syncthreads();

    // ldmatrix per-thread address precompute
    int m_in16 = lane & 15, cselA = lane >> 4;
    uint32_t baseA[4]; int a7[4];
    #pragma unroll
    for (int mf = 0; mf < 4; mf++) {
        int row = warpM * 64 + mf * 16 + m_in16;
        baseA[mf] = sb + SA + row * 256;
        a7[mf] = row & 7;
    }
    int n_in16 = ((lane >> 4) << 3) | (lane & 7);
    int cselB = (lane >> 3) & 1;
    uint32_t baseB[2]; int b7[2];
    #pragma unroll
    for (int p = 0; p < 2; p++) {
        int row = warpN * 32 + p * 16 + n_in16;
        baseB[p] = sb + SB + row * 256;
        b7[p] = row & 7;
    }

    float rowsum[8];
    #pragma unroll
    for (int s = 0; s < 8; s++) rowsum[s] = 0.f;

    int j = 0;
    for (int t = split; t < NTILE; t += NSPLIT, j++) {
        int has_next = (t + NSPLIT < NTILE);
        // Issue next B tile into the other buffer (overlaps compute below)
        if (has_next) {
            uint32_t dx = (uint32_t)(((j + 1) & 1) * 32768);
            #pragma unroll
            for (int i = 0; i < 4; i++) CP_ASYNC16(sdst[i] + dx, gsrc[i]);
            CP_COMMIT();
            #pragma unroll
            for (int i = 0; i < 4; i++) gsrc[i] += gstep;
        }

        uint32_t bufoff = (uint32_t)((j & 1) * 32768);
        float acc[4][4][4];
        #pragma unroll
        for (int mf = 0; mf < 4; mf++)
            #pragma unroll
            for (int nf = 0; nf < 4; nf++)
                #pragma unroll
                for (int q = 0; q < 4; q++) acc[mf][nf][q] = 0.f;

        #pragma unroll
        for (int ks = 0; ks < 8; ks++) {
            uint32_t a[4][4], bb[2][4];
            #pragma unroll
            for (int mf = 0; mf < 4; mf++)
                LDSM4(a[mf], baseA[mf] + (((2 * ks + cselA) ^ a7[mf]) << 4));
            #pragma unroll
            for (int p = 0; p < 2; p++)
                LDSM4(bb[p], baseB[p] + bufoff + (((2 * ks + cselB) ^ b7[p]) << 4));
            #pragma unroll
            for (int mf = 0; mf < 4; mf++)
                #pragma unroll
                for (int nf = 0; nf < 4; nf++)
                    MMA16816(acc[mf][nf], a[mf], bb[nf >> 1][(nf & 1) * 2],
                             bb[nf >> 1][(nf & 1) * 2 + 1]);
        }

        // Epilogue: exp-sum into row accumulators (pad rows corrected in kpick)
        #pragma unroll
        for (int mf = 0; mf < 4; mf++)
            #pragma unroll
            for (int nf = 0; nf < 4; nf++)
                #pragma unroll
                for (int q = 0; q < 4; q++)
                    rowsum[mf * 2 + (q >> 1)] += ex2f(fmaf(acc[mf][nf][q], COEF, -COEF));

        if (has_next) CP_WAIT0();
        __syncthreads();
    }

    // Quad reduce (4 lanes sharing a row), then cross-warpN via smem
    #pragma unroll
    for (int s = 0; s < 8; s++) {
        float v = rowsum[s];
        v += __shfl_xor_sync(0xffffffffu, v, 1);
        v += __shfl_xor_sync(0xffffffffu, v, 2);
        rowsum[s] = v;
    }
    float* red = (float*)(smem + SR);
    if ((lane & 3) == 0) {
        #pragma unroll
        for (int s = 0; s < 8; s++) {
            int row = warpM * 64 + (s >> 1) * 16 + (s & 1) * 8 + (lane >> 2);
            red[warpN * 256 + row] = rowsum[s];
        }
    }
    __syncthreads();
    if (tid < 256) {
        float s = red[tid] + red[256 + tid] + red[512 + tid] + red[768 + tid];
        g_partial[split * B_ROWS + mgrp * 256 + tid] = s;
    }
}

// ---------------------------------------------------------------------------
// Kernel 3a: per-sample loss (parallel gathers). Grid 256 x 256 thr.
// ---------------------------------------------------------------------------
__global__ void kpick(const float* __restrict__ feats,
                      const void* __restrict__ indexes,
                      const void* __restrict__ labels) {
    __shared__ int s64i, s64l;
    int tid = threadIdx.x, lane = tid & 31, w = tid >> 5;
    if (tid == 0) { s64i = sniff_is64(indexes, B_ROWS); s64l = sniff_is64(labels, NFEAT); }
    __syncthreads();
    int b = blockIdx.x * 8 + w;

    float s = (lane < NSPLIT) ? g_partial[lane * B_ROWS + b] : 0.f;
    #pragma unroll
    for (int o = 16; o; o >>= 1) s += __shfl_xor_sync(0xffffffffu, s, o);
    s -= 96.0f * ex2f(-COEF);                    // exact pad-row correction

    long long ix = load_index(indexes, b, s64i);
    if (ix < 0) ix = 0; if (ix >= NFEAT) ix = NFEAT - 1;
    long long tgt = load_index(labels, (int)ix, s64l);
    if (tgt < 0) tgt = 0; if (tgt >= NFEAT) tgt = NFEAT - 1;
    const float* fr = feats + (size_t)tgt * DDIM;
    const float* ir = g_inorm + b * DDIM;
    float d = 0.f;
    #pragma unroll
    for (int k = 0; k < 4; k++) d = fmaf(ir[lane + 32 * k], fr[lane + 32 * k], d);
    #pragma unroll
    for (int o = 16; o; o >>= 1) d += __shfl_xor_sync(0xffffffffu, d, o);
    if (lane == 0) g_loss[b] = (20.0f + logf(s)) - 20.0f * d;
}

// ---------------------------------------------------------------------------
// Kernel 3b: deterministic tree sum of the 2048 losses -> mean
// ---------------------------------------------------------------------------
__global__ void kred(float* __restrict__ out) {
    __shared__ float sm[1024];
    int tid = threadIdx.x;
    sm[tid] = g_loss[tid] + g_loss[tid + 1024];
    __syncthreads();
    #pragma unroll
    for (int off = 512; off > 0; off >>= 1) {
        if (tid < off) sm[tid] += sm[tid + off];
        __syncthreads();
    }
    if (tid == 0) out[0] = sm[0] * (1.0f / (float)B_ROWS);
}

// ---------------------------------------------------------------------------
extern "C" void kernel_launch(void* const* d_in, const int* in_sizes, int n_in,
                              void* d_out, int out_size) {
    const float* inputs = nullptr; const void* indexes = nullptr;
    const void* labels = nullptr;  const float* feats = nullptr;
    for (int i = 0; i < n_in; i++) {
        switch (in_sizes[i]) {
            case B_ROWS * DDIM: inputs = (const float*)d_in[i]; break;
            case B_ROWS:        indexes = d_in[i];              break;
            case NFEAT:         labels = d_in[i];               break;
            case NFEAT * DDIM:  feats = (const float*)d_in[i];  break;
        }
    }
    cudaFuncSetAttribute(kmma, cudaFuncAttributeMaxDynamicSharedMemorySize, 135168);

    knorm<<<B_ROWS, DDIM>>>(inputs);
    kcvt<<<(NFPAD * DDIM) / (256 * 8), 256>>>(feats);
    kmma<<<dim3(NSPLIT, MGRPS), 512, 135168>>>();
    kpick<<<B_ROWS / 8, 256>>>(feats, indexes, labels);
    kred<<<1, 1024>>>((float*)d_out);
}